// round 2
// baseline (speedup 1.0000x reference)
#include <cuda_runtime.h>
#include <cstddef>

namespace {

constexpr int B = 8, T = 2048, H = 256, L = 16;
constexpr int S = 16;                  // t-strip length per block
constexpr int WARPS = 4;               // warp g owns l in [4g, 4g+3]
constexpr int THREADS = WARPS * 32;
constexpr int STRIPS_PER_B = T / S;    // 128
constexpr int NBLOCKS = B * STRIPS_PER_B;  // 1024

struct R8 { float v[8]; };

// Load 8 consecutive floats of row `row` (this lane's H-slice); zeros when OOB
// (implements the reference's zero padding).
__device__ __forceinline__ R8 load_row8(const float* __restrict__ base, int row, int hbase) {
  R8 r;
  if ((unsigned)row < (unsigned)T) {
    const float4* p = reinterpret_cast<const float4*>(base + (size_t)row * H + hbase);
    float4 a = p[0];
    float4 b = p[1];
    r.v[0] = a.x; r.v[1] = a.y; r.v[2] = a.z; r.v[3] = a.w;
    r.v[4] = b.x; r.v[5] = b.y; r.v[6] = b.z; r.v[7] = b.w;
  } else {
#pragma unroll
    for (int j = 0; j < 8; j++) r.v[j] = 0.f;
  }
  return r;
}

__device__ __forceinline__ unsigned long long pack2(float a, float b) {
  unsigned long long r;
  asm("mov.b64 %0, {%1, %2};" : "=l"(r) : "f"(a), "f"(b));
  return r;
}
__device__ __forceinline__ void unpack2(unsigned long long p, float& a, float& b) {
  asm("mov.b64 {%0, %1}, %2;" : "=f"(a), "=f"(b) : "l"(p));
}
__device__ __forceinline__ unsigned long long addx2(unsigned long long a, unsigned long long b) {
  unsigned long long r;
  asm("add.rn.f32x2 %0, %1, %2;" : "=l"(r) : "l"(a), "l"(b));
  return r;
}

__global__ __launch_bounds__(THREADS, 5)
void ffm_main(const float* __restrict__ logits,
              const float* __restrict__ end_w,
              const float* __restrict__ whole_w,
              const float* __restrict__ length_bias,
              float* __restrict__ out) {
  const int strip = blockIdx.x;
  const int b     = strip / STRIPS_PER_B;
  const int s0    = (strip % STRIPS_PER_B) * S;
  const int g     = threadIdx.x >> 5;   // warp id: l in [4g, 4g+3]
  const int lane  = threadIdx.x & 31;
  const int hbase = lane * 8;

  // Weights held in registers for the whole strip.
  float w0[8], w1[8], w2[8], w3[8], ew[8];
#pragma unroll
  for (int j = 0; j < 8; j++) {
    w0[j] = whole_w[(4 * g + 0) * H + hbase + j];
    w1[j] = whole_w[(4 * g + 1) * H + hbase + j];
    w2[j] = whole_w[(4 * g + 2) * H + hbase + j];
    w3[j] = whole_w[(4 * g + 3) * H + hbase + j];
    ew[j] = end_w[hbase + j];
  }
  float4 bias = *reinterpret_cast<const float4*>(length_bias + 4 * g);

  const float* lb = logits + (size_t)b * T * H;

  // 4-row register window. Row (s0 + u - 4g) is loaded at step u into slot (u & 3);
  // at step u (p = u & 3), row r-4g-k lives in slot (p - k) & 3.
  R8 Wn[4];
#pragma unroll
  for (int k = 1; k <= 3; k++)
    Wn[(4 - k) & 3] = load_row8(lb, s0 - 4 * g - k, hbase);

  for (int u0 = 0; u0 < S; u0 += 4) {
#pragma unroll
    for (int p = 0; p < 4; p++) {
      const int r = s0 + u0 + p;

      Wn[p] = load_row8(lb, r - 4 * g, hbase);   // advance window (row r-4g)
      R8 cur;
      if (g == 0) cur = Wn[p];                   // warp 0: cur == window row
      else        cur = load_row8(lb, r, hbase);

      float e = 0.f, a0 = 0.f, a1 = 0.f, a2 = 0.f, a3 = 0.f;
#pragma unroll
      for (int j = 0; j < 8; j++) {
        const float c = cur.v[j];
        e  = fmaf(c, ew[j], e);
        a0 = fmaf(fmaxf(c, Wn[p].v[j]),           w0[j], a0);  // l = 4g
        a1 = fmaf(fmaxf(c, Wn[(p + 3) & 3].v[j]), w1[j], a1);  // l = 4g+1
        a2 = fmaf(fmaxf(c, Wn[(p + 2) & 3].v[j]), w2[j], a2);  // l = 4g+2
        a3 = fmaf(fmaxf(c, Wn[(p + 1) & 3].v[j]), w3[j], a3);  // l = 4g+3
      }
      // Fold end-score partial into each acc (sum over lanes distributes).
      a0 += e; a1 += e; a2 += e; a3 += e;

      // Packed f32x2 butterfly reduction over the warp.
      unsigned long long p01 = pack2(a0, a1);
      unsigned long long p23 = pack2(a2, a3);
#pragma unroll
      for (int s = 16; s > 0; s >>= 1) {
        p01 = addx2(p01, __shfl_xor_sync(0xffffffffu, p01, s));
        p23 = addx2(p23, __shfl_xor_sync(0xffffffffu, p23, s));
      }
      if (lane == 0) {
        float r0, r1, r2, r3;
        unpack2(p01, r0, r1);
        unpack2(p23, r2, r3);
        float4 o;
        o.x = r0 + bias.x; o.y = r1 + bias.y; o.z = r2 + bias.z; o.w = r3 + bias.w;
        *reinterpret_cast<float4*>(out + (size_t)(b * T + r) * L + 4 * g) = o;
      }
    }
  }
}

// relay[b,t] = sum_h max(x[b,t,h], x_pad[b,t+L,h]) * relay_w[h] + relay_b
// One warp per t. Rows beyond T read as zeros (matches jnp.pad), so the max
// against zero is preserved.
__global__ __launch_bounds__(256)
void ffm_relay(const float* __restrict__ logits,
               const float* __restrict__ relay_w,
               const float* __restrict__ relay_b,
               float* __restrict__ relay_out) {
  const int gw   = (blockIdx.x * blockDim.x + threadIdx.x) >> 5;  // global warp = (b,t)
  const int lane = threadIdx.x & 31;
  const int b    = gw / T;
  const int t    = gw % T;
  const int hbase = lane * 8;

  const float* lb = logits + (size_t)b * T * H;
  R8 cur = load_row8(lb, t, hbase);
  R8 nxt = load_row8(lb, t + L, hbase);

  float rel = 0.f;
#pragma unroll
  for (int j = 0; j < 8; j++)
    rel = fmaf(fmaxf(cur.v[j], nxt.v[j]), relay_w[hbase + j], rel);

#pragma unroll
  for (int s = 16; s > 0; s >>= 1)
    rel += __shfl_xor_sync(0xffffffffu, rel, s);

  if (lane == 0) relay_out[(size_t)b * T + t] = rel + relay_b[0];
}

}  // namespace

extern "C" void kernel_launch(void* const* d_in, const int* in_sizes, int n_in,
                              void* d_out, int out_size) {
  const float* logits  = (const float*)d_in[0];
  const float* end_w   = (const float*)d_in[1];
  const float* whole_w = (const float*)d_in[2];
  const float* relay_w = (const float*)d_in[3];
  const float* relay_b = (const float*)d_in[4];
  const float* lbias   = (const float*)d_in[5];

  float* out   = (float*)d_out;                // [B, T, L]
  float* relay = out + (size_t)B * T * L;      // [B, T] appended

  ffm_main<<<NBLOCKS, THREADS>>>(logits, end_w, whole_w, lbias, out);
  ffm_relay<<<(B * T * 32) / 256, 256>>>(logits, relay_w, relay_b, relay);
}